// round 11
// baseline (speedup 1.0000x reference)
#include <cuda_runtime.h>
#include <cuda_bf16.h>
#include <math.h>

#define MM 2048
#define BB 64
#define TT 4
#define DD 128
#define VV 50000

#define PG_GRID 391          // ceil(50000/128)
#define OG_GRID 521          // 521*96 = 50016 >= 50000
#define OG_TILES 3

// Scratch (device globals). g_p layout: [v][b]  (v-major, 64 floats per v row)
__device__ __align__(16) float g_w[BB * VV];
__device__ __align__(16) float g_p[VV * BB];
__device__ int g_is64;

typedef unsigned long long ull;

__device__ __forceinline__ unsigned smem_u32(const void* p) {
    unsigned a;
    asm("{ .reg .u64 t; cvta.to.shared.u64 t, %1; cvt.u32.u64 %0, t; }" : "=r"(a) : "l"(p));
    return a;
}
// bf16x2 pack: lo element first in memory
__device__ __forceinline__ unsigned cvt2bf(float lo, float hi) {
    unsigned r;
    asm("cvt.rn.bf16x2.f32 %0, %1, %2;" : "=r"(r) : "f"(hi), "f"(lo));
    return r;
}
__device__ __forceinline__ void ldsm_x4(unsigned* r, unsigned addr) {
    asm volatile("ldmatrix.sync.aligned.m8n8.x4.shared.b16 {%0,%1,%2,%3}, [%4];"
                 : "=r"(r[0]), "=r"(r[1]), "=r"(r[2]), "=r"(r[3]) : "r"(addr));
}
__device__ __forceinline__ void ldsm_x4_t(unsigned* r, unsigned addr) {
    asm volatile("ldmatrix.sync.aligned.m8n8.x4.trans.shared.b16 {%0,%1,%2,%3}, [%4];"
                 : "=r"(r[0]), "=r"(r[1]), "=r"(r[2]), "=r"(r[3]) : "r"(addr));
}
__device__ __forceinline__ void mma16816(float* c, const unsigned* a, unsigned b0, unsigned b1) {
    asm volatile(
        "mma.sync.aligned.m16n8k16.row.col.f32.bf16.bf16.f32 "
        "{%0,%1,%2,%3}, {%4,%5,%6,%7}, {%8,%9}, {%0,%1,%2,%3};"
        : "+f"(c[0]), "+f"(c[1]), "+f"(c[2]), "+f"(c[3])
        : "r"(a[0]), "r"(a[1]), "r"(a[2]), "r"(a[3]), "r"(b0), "r"(b1));
}

// ---------------------------------------------------------------------------
// Prologue: zero g_w, zero u, dtype probe
// ---------------------------------------------------------------------------
__global__ __launch_bounds__(256) void prologue(const unsigned int* __restrict__ s,
                                                float* __restrict__ u) {
    int blk = blockIdx.x;
    int tid = threadIdx.x;
    if (blk < 3125) {
        int i = blk * 256 + tid;
        float4 z = make_float4(0.f, 0.f, 0.f, 0.f);
        *(float4*)&g_w[(size_t)i * 4] = z;
    } else if (blk == 3125) {
        for (int i = tid; i < BB * DD; i += 256) u[i] = 0.f;
    } else if (tid < 32) {
        unsigned int acc = 0;
        #pragma unroll
        for (int i = tid; i < 256; i += 32) acc |= s[2 * i + 1];
        #pragma unroll
        for (int o = 16; o; o >>= 1) acc |= __shfl_xor_sync(0xffffffffu, acc, o);
        if (tid == 0) g_is64 = (acc == 0) ? 1 : 0;
    }
}

// ---------------------------------------------------------------------------
// Fused attention. g_p is [v][b]: score gather at g_p[tok*BB + b].
// ---------------------------------------------------------------------------
__global__ __launch_bounds__(512) void fused_attn(const void* __restrict__ story,
                                                  int use_p) {
    int b = blockIdx.x;
    int tid = threadIdx.x;
    __shared__ float red[16];

    float* wb = g_w + (size_t)b * VV;
    int is64 = g_is64;
    int toks[4][4];
    float sc[4];

    #pragma unroll
    for (int i = 0; i < 4; i++) {
        int m = tid + i * 512;
        if (is64) {
            const long long* sp = (const long long*)story + (size_t)m * (BB * TT) + b * TT;
            longlong2 t0 = ((const longlong2*)sp)[0];
            longlong2 t1 = ((const longlong2*)sp)[1];
            toks[i][0] = (int)t0.x; toks[i][1] = (int)t0.y;
            toks[i][2] = (int)t1.x; toks[i][3] = (int)t1.y;
        } else {
            int4 tt = *((const int4*)((const int*)story + (size_t)m * (BB * TT) + b * TT));
            toks[i][0] = tt.x; toks[i][1] = tt.y;
            toks[i][2] = tt.z; toks[i][3] = tt.w;
        }
        float s = 0.f;
        if (use_p) {
            #pragma unroll
            for (int t = 0; t < 4; t++)
                if (toks[i][t]) s += __ldg(&g_p[(size_t)toks[i][t] * BB + b]);
        }
        sc[i] = s;
    }

    float prob[4];
    if (use_p) {
        float mx = fmaxf(fmaxf(sc[0], sc[1]), fmaxf(sc[2], sc[3]));
        #pragma unroll
        for (int o = 16; o; o >>= 1) mx = fmaxf(mx, __shfl_xor_sync(0xffffffffu, mx, o));
        if ((tid & 31) == 0) red[tid >> 5] = mx;
        __syncthreads();
        float bm = red[0];
        #pragma unroll
        for (int i = 1; i < 16; i++) bm = fmaxf(bm, red[i]);
        float sum = 0.f;
        #pragma unroll
        for (int i = 0; i < 4; i++) { float e = __expf(sc[i] - bm); sc[i] = e; sum += e; }
        #pragma unroll
        for (int o = 16; o; o >>= 1) sum += __shfl_xor_sync(0xffffffffu, sum, o);
        __syncthreads();
        if ((tid & 31) == 0) red[tid >> 5] = sum;
        __syncthreads();
        float tot = 0.f;
        #pragma unroll
        for (int i = 0; i < 16; i++) tot += red[i];
        float inv = 1.f / tot;
        #pragma unroll
        for (int i = 0; i < 4; i++) prob[i] = sc[i] * inv;
    } else {
        #pragma unroll
        for (int i = 0; i < 4; i++) prob[i] = 1.0f / (float)MM;
    }

    #pragma unroll
    for (int i = 0; i < 4; i++) {
        #pragma unroll
        for (int t = 0; t < 4; t++)
            if (toks[i][t]) atomicAdd(&wb[toks[i][t]], prob[i]);
    }
}

// ---------------------------------------------------------------------------
// p_gemm_mma: p[v][b] = sum_k Ct[v][k] * u[b][k], 512 threads / 16 warps.
// Warp grid 8m x 2n: warp = (v rows 16*mw) x (b cols 32*nh).
// A = C tile [128v x 128k] hi/lo bf16; B = u [64b x 128k] hi/lo bf16.
// smem rows 256B, XOR swizzle chunk16 ^= (row & 7).
// ---------------------------------------------------------------------------
__global__ __launch_bounds__(512, 2) void p_gemm_mma(const float* __restrict__ Ct,
                                                     const float* __restrict__ u) {
    extern __shared__ char dsm[];
    unsigned sbase = smem_u32(dsm);
    const unsigned A_HI = 0, A_LO = 32768, B_HI = 65536, B_LO = 81920;

    int tid = threadIdx.x;
    int wid = tid >> 5;
    int lane = tid & 31;
    int mw = wid & 7;        // A rows [16*mw, +16)
    int nh = wid >> 3;       // B cols [32*nh, +32)
    int vbase = blockIdx.x * 128;

    // ---- stage A: 128 rows x 16 chunk16; 4 iters x 512 threads ----
    #pragma unroll
    for (int q = 0; q < 4; q++) {
        int fi = tid + q * 512;
        int row = fi >> 4;
        int c16 = fi & 15;
        int v = vbase + row;
        float4 f0 = make_float4(0.f, 0.f, 0.f, 0.f), f1 = f0;
        if (v < VV) {
            const float* src = Ct + (size_t)v * DD + c16 * 8;
            f0 = *(const float4*)src;
            f1 = *(const float4*)(src + 4);
        }
        uint4 hi, lo;
        hi.x = cvt2bf(f0.x, f0.y); hi.y = cvt2bf(f0.z, f0.w);
        hi.z = cvt2bf(f1.x, f1.y); hi.w = cvt2bf(f1.z, f1.w);
        float hx, hy, hz, hw;
        hx = __bfloat162float(__float2bfloat16(f0.x));
        hy = __bfloat162float(__float2bfloat16(f0.y));
        hz = __bfloat162float(__float2bfloat16(f0.z));
        hw = __bfloat162float(__float2bfloat16(f0.w));
        lo.x = cvt2bf(f0.x - hx, f0.y - hy); lo.y = cvt2bf(f0.z - hz, f0.w - hw);
        hx = __bfloat162float(__float2bfloat16(f1.x));
        hy = __bfloat162float(__float2bfloat16(f1.y));
        hz = __bfloat162float(__float2bfloat16(f1.z));
        hw = __bfloat162float(__float2bfloat16(f1.w));
        lo.z = cvt2bf(f1.x - hx, f1.y - hy); lo.w = cvt2bf(f1.z - hz, f1.w - hw);
        unsigned off = (unsigned)(row * 256 + ((c16 ^ (row & 7)) << 4));
        *(uint4*)(dsm + A_HI + off) = hi;
        *(uint4*)(dsm + A_LO + off) = lo;
    }
    // ---- stage B: 64 rows (b) x 16 chunk16; 2 iters ----
    #pragma unroll
    for (int q = 0; q < 2; q++) {
        int fi = tid + q * 512;
        int row = fi >> 4;
        int c16 = fi & 15;
        const float* src = u + row * DD + c16 * 8;
        float4 f0 = *(const float4*)src;
        float4 f1 = *(const float4*)(src + 4);
        uint4 hi, lo;
        hi.x = cvt2bf(f0.x, f0.y); hi.y = cvt2bf(f0.z, f0.w);
        hi.z = cvt2bf(f1.x, f1.y); hi.w = cvt2bf(f1.z, f1.w);
        float hx, hy, hz, hw;
        hx = __bfloat162float(__float2bfloat16(f0.x));
        hy = __bfloat162float(__float2bfloat16(f0.y));
        hz = __bfloat162float(__float2bfloat16(f0.z));
        hw = __bfloat162float(__float2bfloat16(f0.w));
        lo.x = cvt2bf(f0.x - hx, f0.y - hy); lo.y = cvt2bf(f0.z - hz, f0.w - hw);
        hx = __bfloat162float(__float2bfloat16(f1.x));
        hy = __bfloat162float(__float2bfloat16(f1.y));
        hz = __bfloat162float(__float2bfloat16(f1.z));
        hw = __bfloat162float(__float2bfloat16(f1.w));
        lo.z = cvt2bf(f1.x - hx, f1.y - hy); lo.w = cvt2bf(f1.z - hz, f1.w - hw);
        unsigned off = (unsigned)(row * 256 + ((c16 ^ (row & 7)) << 4));
        *(uint4*)(dsm + B_HI + off) = hi;
        *(uint4*)(dsm + B_LO + off) = lo;
    }
    __syncthreads();

    int mi = lane >> 3, r8 = lane & 7;
    int rowA = mw * 16 + (mi & 1) * 8 + r8;
    int kselA = mi >> 1;
    unsigned baseA = sbase + (unsigned)rowA * 256;
    int sA = rowA & 7;
    int rowB_off = ((lane >> 4) & 1) * 8 + r8;
    int kselB = (lane >> 3) & 1;

    float acc[4][4];
    #pragma unroll
    for (int na = 0; na < 4; na++)
        #pragma unroll
        for (int j = 0; j < 4; j++) acc[na][j] = 0.f;

    #pragma unroll
    for (int ks = 0; ks < 8; ks++) {
        unsigned a_hi[4], a_lo[4];
        unsigned cA = (unsigned)(((2 * ks + kselA) ^ sA) << 4);
        ldsm_x4(a_hi, baseA + A_HI + cA);
        ldsm_x4(a_lo, baseA + A_LO + cA);
        #pragma unroll
        for (int pa = 0; pa < 2; pa++) {
            int rowB = (nh * 2 + pa) * 16 + rowB_off;
            unsigned baseB = sbase + (unsigned)rowB * 256;
            unsigned cB = (unsigned)(((2 * ks + kselB) ^ (rowB & 7)) << 4);
            unsigned bh[4], bl[4];
            ldsm_x4(bh, baseB + B_HI + cB);
            ldsm_x4(bl, baseB + B_LO + cB);
            mma16816(acc[2 * pa],     a_hi, bh[0], bh[1]);
            mma16816(acc[2 * pa],     a_hi, bl[0], bl[1]);
            mma16816(acc[2 * pa],     a_lo, bh[0], bh[1]);
            mma16816(acc[2 * pa + 1], a_hi, bh[2], bh[3]);
            mma16816(acc[2 * pa + 1], a_hi, bl[2], bl[3]);
            mma16816(acc[2 * pa + 1], a_lo, bh[2], bh[3]);
        }
    }

    int v0 = vbase + mw * 16 + (lane >> 2);
    int bq = (lane & 3) * 2;
    #pragma unroll
    for (int na = 0; na < 4; na++) {
        int b0 = nh * 32 + na * 8 + bq;
        if (v0 < VV)
            *(float2*)&g_p[(size_t)v0 * BB + b0] = make_float2(acc[na][0], acc[na][1]);
        if (v0 + 8 < VV)
            *(float2*)&g_p[(size_t)(v0 + 8) * BB + b0] = make_float2(acc[na][2], acc[na][3]);
    }
}

// ---------------------------------------------------------------------------
// o_gemm_mma: u[b][d] += sum_v w[b][v] * Ct[v][d]  via mma.sync, 3-term split.
// Grid 521 x 3 tiles of 32 v (grid-limited parallelism fix).
// ---------------------------------------------------------------------------
__global__ __launch_bounds__(256) void o_gemm_mma(const float* __restrict__ Ct,
                                                  float* __restrict__ u,
                                                  int do_zero) {
    __shared__ __align__(16) char osm[24576];
    const unsigned C_HI = 0, C_LO = 8192, W_HI = 16384, W_LO = 20480;
    unsigned sbase = smem_u32(osm);

    int tid = threadIdx.x;
    int wid = tid >> 5;
    int lane = tid & 31;
    int mw = wid & 3;
    int nw = wid >> 2;
    int vstart = blockIdx.x * (OG_TILES * 32);

    int sc_row = tid >> 5, sc4 = tid & 31;

    float4 rc[4], rw[2];
    {
        int vb = vstart;
        #pragma unroll
        for (int q = 0; q < 4; q++) {
            int v = vb + sc_row + q * 8;
            rc[q] = make_float4(0.f, 0.f, 0.f, 0.f);
            if (v < VV) rc[q] = *(const float4*)(Ct + (size_t)v * DD + sc4 * 4);
        }
        #pragma unroll
        for (int q = 0; q < 2; q++) {
            int fi = tid + q * 256;
            int b_ = fi >> 3, v4 = fi & 7;
            int v = vb + v4 * 4;
            rw[q] = make_float4(0.f, 0.f, 0.f, 0.f);
            if (v < VV) rw[q] = *(const float4*)(g_w + (size_t)b_ * VV + v);
        }
    }

    float acc[8][4];
    #pragma unroll
    for (int na = 0; na < 8; na++)
        #pragma unroll
        for (int j = 0; j < 4; j++) acc[na][j] = 0.f;

    int g = lane >> 3, r8 = lane & 7;
    unsigned a_roff = (unsigned)(((g >> 1) * 8 + r8) * 128
                                 + (((mw * 2 + (g & 1)) ^ r8) << 4));
    unsigned b_rbase = (unsigned)(((g & 1) * 8 + r8) * 256);
    int b_cxor = (nw * 8 + (g >> 1));

    #pragma unroll 1
    for (int t = 0; t < OG_TILES; t++) {
        __syncthreads();
        #pragma unroll
        for (int q = 0; q < 4; q++) {
            int row = sc_row + q * 8;
            float4 f = rc[q];
            float hx = __bfloat162float(__float2bfloat16(f.x));
            float hy = __bfloat162float(__float2bfloat16(f.y));
            float hz = __bfloat162float(__float2bfloat16(f.z));
            float hw = __bfloat162float(__float2bfloat16(f.w));
            uint2 hi = make_uint2(cvt2bf(f.x, f.y), cvt2bf(f.z, f.w));
            uint2 lo = make_uint2(cvt2bf(f.x - hx, f.y - hy), cvt2bf(f.z - hz, f.w - hw));
            unsigned off = (unsigned)(row * 256 + (((sc4 >> 1) ^ (row & 7)) << 4)
                                      + (sc4 & 1) * 8);
            *(uint2*)(osm + C_HI + off) = hi;
            *(uint2*)(osm + C_LO + off) = lo;
        }
        #pragma unroll
        for (int q = 0; q < 2; q++) {
            int fi = tid + q * 256;
            int b_ = fi >> 3, v4 = fi & 7;
            float fv[4] = {rw[q].x, rw[q].y, rw[q].z, rw[q].w};
            #pragma unroll
            for (int j = 0; j < 4; j++) {
                int vr = v4 * 4 + j;
                __nv_bfloat16 h = __float2bfloat16(fv[j]);
                __nv_bfloat16 l = __float2bfloat16(fv[j] - __bfloat162float(h));
                unsigned off = (unsigned)(vr * 128 + (((b_ >> 3) ^ (vr & 7)) << 4)
                                          + (b_ & 7) * 2);
                *(__nv_bfloat16*)(osm + W_HI + off) = h;
                *(__nv_bfloat16*)(osm + W_LO + off) = l;
            }
        }
        __syncthreads();

        if (t + 1 < OG_TILES) {
            int vb = vstart + (t + 1) * 32;
            #pragma unroll
            for (int q = 0; q < 4; q++) {
                int v = vb + sc_row + q * 8;
                rc[q] = make_float4(0.f, 0.f, 0.f, 0.f);
                if (v < VV) rc[q] = *(const float4*)(Ct + (size_t)v * DD + sc4 * 4);
            }
            #pragma unroll
            for (int q = 0; q < 2; q++) {
                int fi = tid + q * 256;
                int b_ = fi >> 3, v4 = fi & 7;
                int v = vb + v4 * 4;
                rw[q] = make_float4(0.f, 0.f, 0.f, 0.f);
                if (v < VV) rw[q] = *(const float4*)(g_w + (size_t)b_ * VV + v);
            }
        }

        #pragma unroll
        for (int ks = 0; ks < 2; ks++) {
            unsigned a_hi[4], a_lo[4];
            unsigned aoff = (unsigned)(ks * 16 * 128) + a_roff;
            ldsm_x4_t(a_hi, sbase + W_HI + aoff);
            ldsm_x4_t(a_lo, sbase + W_LO + aoff);
            #pragma unroll
            for (int pn = 0; pn < 4; pn++) {
                unsigned boff = (unsigned)(ks * 16 * 256) + b_rbase
                              + (unsigned)(((b_cxor + pn * 2) ^ r8) << 4);
                unsigned bh[4], bl[4];
                ldsm_x4_t(bh, sbase + C_HI + boff);
                ldsm_x4_t(bl, sbase + C_LO + boff);
                mma16816(acc[2 * pn],     a_hi, bh[0], bh[1]);
                mma16816(acc[2 * pn],     a_hi, bl[0], bl[1]);
                mma16816(acc[2 * pn],     a_lo, bh[0], bh[1]);
                mma16816(acc[2 * pn + 1], a_hi, bh[2], bh[3]);
                mma16816(acc[2 * pn + 1], a_hi, bl[2], bl[3]);
                mma16816(acc[2 * pn + 1], a_lo, bh[2], bh[3]);
            }
        }
    }

    int br0 = mw * 16 + (lane >> 2);
    int nq = (lane & 3) * 2;
    #pragma unroll
    for (int na = 0; na < 8; na++) {
        int d = nw * 64 + na * 8 + nq;
        atomicAdd(&u[br0 * DD + d],       acc[na][0]);
        atomicAdd(&u[br0 * DD + d + 1],   acc[na][1]);
        atomicAdd(&u[(br0 + 8) * DD + d],     acc[na][2]);
        atomicAdd(&u[(br0 + 8) * DD + d + 1], acc[na][3]);
    }

    if (do_zero) {
        float4 z = make_float4(0.f, 0.f, 0.f, 0.f);
        for (int idx = tid; idx < 64 * 24; idx += 256) {
            int b_ = idx / 24;
            int v = vstart + (idx % 24) * 4;
            if (v < VV)
                *(float4*)&g_w[(size_t)b_ * VV + v] = z;
        }
    }
}

// ---------------------------------------------------------------------------
extern "C" void kernel_launch(void* const* d_in, const int* in_sizes, int n_in,
                              void* d_out, int out_size) {
    int si = 0, ci = 1;
    if (n_in >= 2 && in_sizes[0] > in_sizes[1]) { si = 1; ci = 0; }
    const void* story = d_in[si];
    const float* C = (const float*)d_in[ci];
    float* u = (float*)d_out;

    const int PG_SMEM = 98304;   // A hi/lo 32K*2 + B hi/lo 16K*2
    static int smem_set = 0;
    if (!smem_set) {
        cudaFuncSetAttribute(p_gemm_mma, cudaFuncAttributeMaxDynamicSharedMemorySize, PG_SMEM);
        smem_set = 1;
    }

    prologue<<<3127, 256>>>((const unsigned int*)story, u);

    for (int h = 0; h < 3; h++) {
        if (h) p_gemm_mma<<<PG_GRID, 512, PG_SMEM>>>(C + (size_t)h * VV * DD, u);
        fused_attn<<<BB, 512>>>(story, h > 0 ? 1 : 0);
        o_gemm_mma<<<OG_GRID, 256>>>(C + (size_t)(h + 1) * VV * DD, u, h < 2 ? 1 : 0);
    }
}

// round 13
// speedup vs baseline: 1.2806x; 1.2806x over previous
#include <cuda_runtime.h>
#include <cuda_bf16.h>
#include <math.h>

#define MM 2048
#define BB 64
#define TT 4
#define DD 128
#define VV 50000

#define PG_GRID 391          // ceil(50000/128)
#define OG_GRID 261          // 261*192 = 50112 >= 50000
#define OG_TILES 6

// Scratch (device globals). g_p layout: [v][b]  (v-major, 64 floats per v row)
__device__ __align__(16) float g_w[BB * VV];
__device__ __align__(16) float g_p[VV * BB];
__device__ __align__(16) float g_s[BB * MM];     // exp(score - local max), [b][m]
__device__ __align__(16) float2 g_red[BB * 4];   // per (b, quarter): {max, sum}
__device__ int g_is64;

typedef unsigned long long ull;

__device__ __forceinline__ unsigned smem_u32(const void* p) {
    unsigned a;
    asm("{ .reg .u64 t; cvta.to.shared.u64 t, %1; cvt.u32.u64 %0, t; }" : "=r"(a) : "l"(p));
    return a;
}
// bf16x2 pack: lo element first in memory
__device__ __forceinline__ unsigned cvt2bf(float lo, float hi) {
    unsigned r;
    asm("cvt.rn.bf16x2.f32 %0, %1, %2;" : "=r"(r) : "f"(hi), "f"(lo));
    return r;
}
__device__ __forceinline__ void ldsm_x4(unsigned* r, unsigned addr) {
    asm volatile("ldmatrix.sync.aligned.m8n8.x4.shared.b16 {%0,%1,%2,%3}, [%4];"
                 : "=r"(r[0]), "=r"(r[1]), "=r"(r[2]), "=r"(r[3]) : "r"(addr));
}
__device__ __forceinline__ void ldsm_x4_t(unsigned* r, unsigned addr) {
    asm volatile("ldmatrix.sync.aligned.m8n8.x4.trans.shared.b16 {%0,%1,%2,%3}, [%4];"
                 : "=r"(r[0]), "=r"(r[1]), "=r"(r[2]), "=r"(r[3]) : "r"(addr));
}
__device__ __forceinline__ void mma16816(float* c, const unsigned* a, unsigned b0, unsigned b1) {
    asm volatile(
        "mma.sync.aligned.m16n8k16.row.col.f32.bf16.bf16.f32 "
        "{%0,%1,%2,%3}, {%4,%5,%6,%7}, {%8,%9}, {%0,%1,%2,%3};"
        : "+f"(c[0]), "+f"(c[1]), "+f"(c[2]), "+f"(c[3])
        : "r"(a[0]), "r"(a[1]), "r"(a[2]), "r"(a[3]), "r"(b0), "r"(b1));
}

// ---------------------------------------------------------------------------
// Prologue: zero g_w, zero u, dtype probe
// ---------------------------------------------------------------------------
__global__ __launch_bounds__(256) void prologue(const unsigned int* __restrict__ s,
                                                float* __restrict__ u) {
    int blk = blockIdx.x;
    int tid = threadIdx.x;
    if (blk < 3125) {
        int i = blk * 256 + tid;
        float4 z = make_float4(0.f, 0.f, 0.f, 0.f);
        *(float4*)&g_w[(size_t)i * 4] = z;
    } else if (blk == 3125) {
        for (int i = tid; i < BB * DD; i += 256) u[i] = 0.f;
    } else if (tid < 32) {
        unsigned int acc = 0;
        #pragma unroll
        for (int i = tid; i < 256; i += 32) acc |= s[2 * i + 1];
        #pragma unroll
        for (int o = 16; o; o >>= 1) acc |= __shfl_xor_sync(0xffffffffu, acc, o);
        if (tid == 0) g_is64 = (acc == 0) ? 1 : 0;
    }
}

// ---------------------------------------------------------------------------
// Load 4 tokens of (m, b) from story (int64 or int32)
// ---------------------------------------------------------------------------
__device__ __forceinline__ void load_toks(const void* story, int is64, int m, int b,
                                          int* toks) {
    if (is64) {
        const long long* sp = (const long long*)story + (size_t)m * (BB * TT) + b * TT;
        longlong2 t0 = ((const longlong2*)sp)[0];
        longlong2 t1 = ((const longlong2*)sp)[1];
        toks[0] = (int)t0.x; toks[1] = (int)t0.y;
        toks[2] = (int)t1.x; toks[3] = (int)t1.y;
    } else {
        int4 tt = *((const int4*)((const int*)story + (size_t)m * (BB * TT) + b * TT));
        toks[0] = tt.x; toks[1] = tt.y; toks[2] = tt.z; toks[3] = tt.w;
    }
}

// ---------------------------------------------------------------------------
// attn_score: 256 blocks = (b, quarter). Each thread one m. Computes score
// via p-gather, local softmax numerator exp(s - Lmax), per-quarter (max, sum).
// ---------------------------------------------------------------------------
__global__ __launch_bounds__(512) void attn_score(const void* __restrict__ story) {
    int b = blockIdx.x >> 2;
    int q = blockIdx.x & 3;
    int tid = threadIdx.x;
    int m = q * 512 + tid;
    __shared__ float red[16];

    int is64 = g_is64;
    int toks[4];
    load_toks(story, is64, m, b, toks);

    float s = 0.f;
    #pragma unroll
    for (int t = 0; t < 4; t++)
        if (toks[t]) s += __ldg(&g_p[(size_t)toks[t] * BB + b]);

    // block max
    float mx = s;
    #pragma unroll
    for (int o = 16; o; o >>= 1) mx = fmaxf(mx, __shfl_xor_sync(0xffffffffu, mx, o));
    if ((tid & 31) == 0) red[tid >> 5] = mx;
    __syncthreads();
    float bm = red[0];
    #pragma unroll
    for (int i = 1; i < 16; i++) bm = fmaxf(bm, red[i]);

    float e = __expf(s - bm);
    g_s[(size_t)b * MM + m] = e;

    float sum = e;
    #pragma unroll
    for (int o = 16; o; o >>= 1) sum += __shfl_xor_sync(0xffffffffu, sum, o);
    __syncthreads();
    if ((tid & 31) == 0) red[tid >> 5] = sum;
    __syncthreads();
    if (tid == 0) {
        float tot = 0.f;
        #pragma unroll
        for (int i = 0; i < 16; i++) tot += red[i];
        g_red[b * 4 + q] = make_float2(bm, tot);
    }
}

// ---------------------------------------------------------------------------
// attn_scatter: 256 blocks = (b, quarter). Combines 4 per-quarter (max,sum)
// into exact softmax scale, scatters prob into g_w. Hop 0: uniform prob.
// ---------------------------------------------------------------------------
__global__ __launch_bounds__(512) void attn_scatter(const void* __restrict__ story,
                                                    int use_p) {
    int b = blockIdx.x >> 2;
    int q = blockIdx.x & 3;
    int tid = threadIdx.x;
    int m = q * 512 + tid;

    int is64 = g_is64;
    int toks[4];
    load_toks(story, is64, m, b, toks);

    float prob;
    if (use_p) {
        float2 r0 = g_red[b * 4 + 0];
        float2 r1 = g_red[b * 4 + 1];
        float2 r2 = g_red[b * 4 + 2];
        float2 r3 = g_red[b * 4 + 3];
        float M = fmaxf(fmaxf(r0.x, r1.x), fmaxf(r2.x, r3.x));
        float total = r0.y * __expf(r0.x - M) + r1.y * __expf(r1.x - M)
                    + r2.y * __expf(r2.x - M) + r3.y * __expf(r3.x - M);
        float myb = (q == 0) ? r0.x : (q == 1) ? r1.x : (q == 2) ? r2.x : r3.x;
        float scale = __expf(myb - M) / total;
        prob = g_s[(size_t)b * MM + m] * scale;
    } else {
        prob = 1.0f / (float)MM;
    }

    float* wb = g_w + (size_t)b * VV;
    #pragma unroll
    for (int t = 0; t < 4; t++)
        if (toks[t]) atomicAdd(&wb[toks[t]], prob);
}

// ---------------------------------------------------------------------------
// p_gemm_mma: p[v][b] = sum_k Ct[v][k] * u[b][k], 512 threads / 16 warps.
// (verified; unchanged from R10 — dur equal to 256-thr version, fewer regs)
// ---------------------------------------------------------------------------
__global__ __launch_bounds__(512, 2) void p_gemm_mma(const float* __restrict__ Ct,
                                                     const float* __restrict__ u) {
    extern __shared__ char dsm[];
    unsigned sbase = smem_u32(dsm);
    const unsigned A_HI = 0, A_LO = 32768, B_HI = 65536, B_LO = 81920;

    int tid = threadIdx.x;
    int wid = tid >> 5;
    int lane = tid & 31;
    int mw = wid & 7;
    int nh = wid >> 3;
    int vbase = blockIdx.x * 128;

    #pragma unroll
    for (int q = 0; q < 4; q++) {
        int fi = tid + q * 512;
        int row = fi >> 4;
        int c16 = fi & 15;
        int v = vbase + row;
        float4 f0 = make_float4(0.f, 0.f, 0.f, 0.f), f1 = f0;
        if (v < VV) {
            const float* src = Ct + (size_t)v * DD + c16 * 8;
            f0 = *(const float4*)src;
            f1 = *(const float4*)(src + 4);
        }
        uint4 hi, lo;
        hi.x = cvt2bf(f0.x, f0.y); hi.y = cvt2bf(f0.z, f0.w);
        hi.z = cvt2bf(f1.x, f1.y); hi.w = cvt2bf(f1.z, f1.w);
        float hx, hy, hz, hw;
        hx = __bfloat162float(__float2bfloat16(f0.x));
        hy = __bfloat162float(__float2bfloat16(f0.y));
        hz = __bfloat162float(__float2bfloat16(f0.z));
        hw = __bfloat162float(__float2bfloat16(f0.w));
        lo.x = cvt2bf(f0.x - hx, f0.y - hy); lo.y = cvt2bf(f0.z - hz, f0.w - hw);
        hx = __bfloat162float(__float2bfloat16(f1.x));
        hy = __bfloat162float(__float2bfloat16(f1.y));
        hz = __bfloat162float(__float2bfloat16(f1.z));
        hw = __bfloat162float(__float2bfloat16(f1.w));
        lo.z = cvt2bf(f1.x - hx, f1.y - hy); lo.w = cvt2bf(f1.z - hz, f1.w - hw);
        unsigned off = (unsigned)(row * 256 + ((c16 ^ (row & 7)) << 4));
        *(uint4*)(dsm + A_HI + off) = hi;
        *(uint4*)(dsm + A_LO + off) = lo;
    }
    #pragma unroll
    for (int q = 0; q < 2; q++) {
        int fi = tid + q * 512;
        int row = fi >> 4;
        int c16 = fi & 15;
        const float* src = u + row * DD + c16 * 8;
        float4 f0 = *(const float4*)src;
        float4 f1 = *(const float4*)(src + 4);
        uint4 hi, lo;
        hi.x = cvt2bf(f0.x, f0.y); hi.y = cvt2bf(f0.z, f0.w);
        hi.z = cvt2bf(f1.x, f1.y); hi.w = cvt2bf(f1.z, f1.w);
        float hx, hy, hz, hw;
        hx = __bfloat162float(__float2bfloat16(f0.x));
        hy = __bfloat162float(__float2bfloat16(f0.y));
        hz = __bfloat162float(__float2bfloat16(f0.z));
        hw = __bfloat162float(__float2bfloat16(f0.w));
        lo.x = cvt2bf(f0.x - hx, f0.y - hy); lo.y = cvt2bf(f0.z - hz, f0.w - hw);
        hx = __bfloat162float(__float2bfloat16(f1.x));
        hy = __bfloat162float(__float2bfloat16(f1.y));
        hz = __bfloat162float(__float2bfloat16(f1.z));
        hw = __bfloat162float(__float2bfloat16(f1.w));
        lo.z = cvt2bf(f1.x - hx, f1.y - hy); lo.w = cvt2bf(f1.z - hz, f1.w - hw);
        unsigned off = (unsigned)(row * 256 + ((c16 ^ (row & 7)) << 4));
        *(uint4*)(dsm + B_HI + off) = hi;
        *(uint4*)(dsm + B_LO + off) = lo;
    }
    __syncthreads();

    int mi = lane >> 3, r8 = lane & 7;
    int rowA = mw * 16 + (mi & 1) * 8 + r8;
    int kselA = mi >> 1;
    unsigned baseA = sbase + (unsigned)rowA * 256;
    int sA = rowA & 7;
    int rowB_off = ((lane >> 4) & 1) * 8 + r8;
    int kselB = (lane >> 3) & 1;

    float acc[4][4];
    #pragma unroll
    for (int na = 0; na < 4; na++)
        #pragma unroll
        for (int j = 0; j < 4; j++) acc[na][j] = 0.f;

    #pragma unroll
    for (int ks = 0; ks < 8; ks++) {
        unsigned a_hi[4], a_lo[4];
        unsigned cA = (unsigned)(((2 * ks + kselA) ^ sA) << 4);
        ldsm_x4(a_hi, baseA + A_HI + cA);
        ldsm_x4(a_lo, baseA + A_LO + cA);
        #pragma unroll
        for (int pa = 0; pa < 2; pa++) {
            int rowB = (nh * 2 + pa) * 16 + rowB_off;
            unsigned baseB = sbase + (unsigned)rowB * 256;
            unsigned cB = (unsigned)(((2 * ks + kselB) ^ (rowB & 7)) << 4);
            unsigned bh[4], bl[4];
            ldsm_x4(bh, baseB + B_HI + cB);
            ldsm_x4(bl, baseB + B_LO + cB);
            mma16816(acc[2 * pa],     a_hi, bh[0], bh[1]);
            mma16816(acc[2 * pa],     a_hi, bl[0], bl[1]);
            mma16816(acc[2 * pa],     a_lo, bh[0], bh[1]);
            mma16816(acc[2 * pa + 1], a_hi, bh[2], bh[3]);
            mma16816(acc[2 * pa + 1], a_hi, bl[2], bl[3]);
            mma16816(acc[2 * pa + 1], a_lo, bh[2], bh[3]);
        }
    }

    int v0 = vbase + mw * 16 + (lane >> 2);
    int bq = (lane & 3) * 2;
    #pragma unroll
    for (int na = 0; na < 4; na++) {
        int b0 = nh * 32 + na * 8 + bq;
        if (v0 < VV)
            *(float2*)&g_p[(size_t)v0 * BB + b0] = make_float2(acc[na][0], acc[na][1]);
        if (v0 + 8 < VV)
            *(float2*)&g_p[(size_t)(v0 + 8) * BB + b0] = make_float2(acc[na][2], acc[na][3]);
    }
}

// ---------------------------------------------------------------------------
// o_gemm_mma: u[b][d] += sum_v w[b][v] * Ct[v][d]. REVERTED to R9 shape:
// grid 261 x 6 tiles (fewer K-splits -> half the u-atomics of R10).
// ---------------------------------------------------------------------------
__global__ __launch_bounds__(256) void o_gemm_mma(const float* __restrict__ Ct,
                                                  float* __restrict__ u,
                                                  int do_zero) {
    __shared__ __align__(16) char osm[24576];
    const unsigned C_HI = 0, C_LO = 8192, W_HI = 16384, W_LO = 20480;
    unsigned sbase = smem_u32(osm);

    int tid = threadIdx.x;
    int wid = tid >> 5;
    int lane = tid & 31;
    int mw = wid & 3;
    int nw = wid >> 2;
    int vstart = blockIdx.x * (OG_TILES * 32);

    int sc_row = tid >> 5, sc4 = tid & 31;

    float4 rc[4], rw[2];
    {
        int vb = vstart;
        #pragma unroll
        for (int q = 0; q < 4; q++) {
            int v = vb + sc_row + q * 8;
            rc[q] = make_float4(0.f, 0.f, 0.f, 0.f);
            if (v < VV) rc[q] = *(const float4*)(Ct + (size_t)v * DD + sc4 * 4);
        }
        #pragma unroll
        for (int q = 0; q < 2; q++) {
            int fi = tid + q * 256;
            int b_ = fi >> 3, v4 = fi & 7;
            int v = vb + v4 * 4;
            rw[q] = make_float4(0.f, 0.f, 0.f, 0.f);
            if (v < VV) rw[q] = *(const float4*)(g_w + (size_t)b_ * VV + v);
        }
    }

    float acc[8][4];
    #pragma unroll
    for (int na = 0; na < 8; na++)
        #pragma unroll
        for (int j = 0; j < 4; j++) acc[na][j] = 0.f;

    int g = lane >> 3, r8 = lane & 7;
    unsigned a_roff = (unsigned)(((g >> 1) * 8 + r8) * 128
                                 + (((mw * 2 + (g & 1)) ^ r8) << 4));
    unsigned b_rbase = (unsigned)(((g & 1) * 8 + r8) * 256);
    int b_cxor = (nw * 8 + (g >> 1));

    #pragma unroll 1
    for (int t = 0; t < OG_TILES; t++) {
        __syncthreads();
        #pragma unroll
        for (int q = 0; q < 4; q++) {
            int row = sc_row + q * 8;
            float4 f = rc[q];
            float hx = __bfloat162float(__float2bfloat16(f.x));
            float hy = __bfloat162float(__float2bfloat16(f.y));
            float hz = __bfloat162float(__float2bfloat16(f.z));
            float hw = __bfloat162float(__float2bfloat16(f.w));
            uint2 hi = make_uint2(cvt2bf(f.x, f.y), cvt2bf(f.z, f.w));
            uint2 lo = make_uint2(cvt2bf(f.x - hx, f.y - hy), cvt2bf(f.z - hz, f.w - hw));
            unsigned off = (unsigned)(row * 256 + (((sc4 >> 1) ^ (row & 7)) << 4)
                                      + (sc4 & 1) * 8);
            *(uint2*)(osm + C_HI + off) = hi;
            *(uint2*)(osm + C_LO + off) = lo;
        }
        #pragma unroll
        for (int q = 0; q < 2; q++) {
            int fi = tid + q * 256;
            int b_ = fi >> 3, v4 = fi & 7;
            float fv[4] = {rw[q].x, rw[q].y, rw[q].z, rw[q].w};
            #pragma unroll
            for (int j = 0; j < 4; j++) {
                int vr = v4 * 4 + j;
                __nv_bfloat16 h = __float2bfloat16(fv[j]);
                __nv_bfloat16 l = __float2bfloat16(fv[j] - __bfloat162float(h));
                unsigned off = (unsigned)(vr * 128 + (((b_ >> 3) ^ (vr & 7)) << 4)
                                          + (b_ & 7) * 2);
                *(__nv_bfloat16*)(osm + W_HI + off) = h;
                *(__nv_bfloat16*)(osm + W_LO + off) = l;
            }
        }
        __syncthreads();

        if (t + 1 < OG_TILES) {
            int vb = vstart + (t + 1) * 32;
            #pragma unroll
            for (int q = 0; q < 4; q++) {
                int v = vb + sc_row + q * 8;
                rc[q] = make_float4(0.f, 0.f, 0.f, 0.f);
                if (v < VV) rc[q] = *(const float4*)(Ct + (size_t)v * DD + sc4 * 4);
            }
            #pragma unroll
            for (int q = 0; q < 2; q++) {
                int fi = tid + q * 256;
                int b_ = fi >> 3, v4 = fi & 7;
                int v = vb + v4 * 4;
                rw[q] = make_float4(0.f, 0.f, 0.f, 0.f);
                if (v < VV) rw[q] = *(const float4*)(g_w + (size_t)b_ * VV + v);
            }
        }

        #pragma unroll
        for (int ks = 0; ks < 2; ks++) {
            unsigned a_hi[4], a_lo[4];
            unsigned aoff = (unsigned)(ks * 16 * 128) + a_roff;
            ldsm_x4_t(a_hi, sbase + W_HI + aoff);
            ldsm_x4_t(a_lo, sbase + W_LO + aoff);
            #pragma unroll
            for (int pn = 0; pn < 4; pn++) {
                unsigned boff = (unsigned)(ks * 16 * 256) + b_rbase
                              + (unsigned)(((b_cxor + pn * 2) ^ r8) << 4);
                unsigned bh[4], bl[4];
                ldsm_x4_t(bh, sbase + C_HI + boff);
                ldsm_x4_t(bl, sbase + C_LO + boff);
                mma16816(acc[2 * pn],     a_hi, bh[0], bh[1]);
                mma16816(acc[2 * pn],     a_hi, bl[0], bl[1]);
                mma16816(acc[2 * pn],     a_lo, bh[0], bh[1]);
                mma16816(acc[2 * pn + 1], a_hi, bh[2], bh[3]);
                mma16816(acc[2 * pn + 1], a_hi, bl[2], bl[3]);
                mma16816(acc[2 * pn + 1], a_lo, bh[2], bh[3]);
            }
        }
    }

    int br0 = mw * 16 + (lane >> 2);
    int nq = (lane & 3) * 2;
    #pragma unroll
    for (int na = 0; na < 8; na++) {
        int d = nw * 64 + na * 8 + nq;
        atomicAdd(&u[br0 * DD + d],       acc[na][0]);
        atomicAdd(&u[br0 * DD + d + 1],   acc[na][1]);
        atomicAdd(&u[(br0 + 8) * DD + d],     acc[na][2]);
        atomicAdd(&u[(br0 + 8) * DD + d + 1], acc[na][3]);
    }

    if (do_zero) {
        float4 z = make_float4(0.f, 0.f, 0.f, 0.f);
        for (int idx = tid; idx < 64 * 48; idx += 256) {
            int b_ = idx / 48;
            int v = vstart + (idx % 48) * 4;
            if (v < VV)
                *(float4*)&g_w[(size_t)b_ * VV + v] = z;
        }
    }
}

// ---------------------------------------------------------------------------
extern "C" void kernel_launch(void* const* d_in, const int* in_sizes, int n_in,
                              void* d_out, int out_size) {
    int si = 0, ci = 1;
    if (n_in >= 2 && in_sizes[0] > in_sizes[1]) { si = 1; ci = 0; }
    const void* story = d_in[si];
    const float* C = (const float*)d_in[ci];
    float* u = (float*)d_out;

    const int PG_SMEM = 98304;   // A hi/lo 32K*2 + B hi/lo 16K*2
    static int smem_set = 0;
    if (!smem_set) {
        cudaFuncSetAttribute(p_gemm_mma, cudaFuncAttributeMaxDynamicSharedMemorySize, PG_SMEM);
        smem_set = 1;
    }

    prologue<<<3127, 256>>>((const unsigned int*)story, u);

    for (int h = 0; h < 3; h++) {
        if (h) {
            p_gemm_mma<<<PG_GRID, 512, PG_SMEM>>>(C + (size_t)h * VV * DD, u);
            attn_score<<<BB * 4, 512>>>(story);
        }
        attn_scatter<<<BB * 4, 512>>>(story, h > 0 ? 1 : 0);
        o_gemm_mma<<<OG_GRID, 256>>>(C + (size_t)(h + 1) * VV * DD, u, h < 2 ? 1 : 0);
    }
}

// round 14
// speedup vs baseline: 1.4118x; 1.1024x over previous
#include <cuda_runtime.h>
#include <cuda_bf16.h>
#include <math.h>

#define MM 2048
#define BB 64
#define TT 4
#define DD 128
#define VV 50000

#define PG_GRID 391          // ceil(50000/128)
#define OG_GRID 261          // 261*192 = 50112 >= 50000
#define OG_TILES 6

// Scratch (device globals). g_p layout: [v][b]  (v-major, 64 floats per v row)
__device__ __align__(16) float g_w[BB * VV];
__device__ __align__(16) float g_p[VV * BB];
__device__ __align__(16) float g_s[BB * MM];     // exp(score - local max), [b][m]
__device__ __align__(16) float2 g_red[BB * 4];   // per (b, quarter): {max, sum}
__device__ __align__(16) float g_part[OG_GRID * BB * DD];   // o_gemm partials
__device__ int g_is64;

typedef unsigned long long ull;

__device__ __forceinline__ unsigned smem_u32(const void* p) {
    unsigned a;
    asm("{ .reg .u64 t; cvta.to.shared.u64 t, %1; cvt.u32.u64 %0, t; }" : "=r"(a) : "l"(p));
    return a;
}
// bf16x2 pack (rn): lo element first in memory
__device__ __forceinline__ unsigned cvt2bf(float lo, float hi) {
    unsigned r;
    asm("cvt.rn.bf16x2.f32 %0, %1, %2;" : "=r"(r) : "f"(hi), "f"(lo));
    return r;
}
// Truncation split: hi = top-16-bits of each float (exact bf16), lo = f - hi
// (exactly representable: <=8 significand bits). hi+lo == f exactly.
__device__ __forceinline__ void split2(float x, float y, unsigned& hi, unsigned& lo) {
    unsigned bx = __float_as_uint(x), by = __float_as_uint(y);
    hi = __byte_perm(bx, by, 0x7632);
    float lx = x - __uint_as_float(bx & 0xFFFF0000u);
    float ly = y - __uint_as_float(by & 0xFFFF0000u);
    lo = cvt2bf(lx, ly);
}
__device__ __forceinline__ void ldsm_x4(unsigned* r, unsigned addr) {
    asm volatile("ldmatrix.sync.aligned.m8n8.x4.shared.b16 {%0,%1,%2,%3}, [%4];"
                 : "=r"(r[0]), "=r"(r[1]), "=r"(r[2]), "=r"(r[3]) : "r"(addr));
}
__device__ __forceinline__ void ldsm_x4_t(unsigned* r, unsigned addr) {
    asm volatile("ldmatrix.sync.aligned.m8n8.x4.trans.shared.b16 {%0,%1,%2,%3}, [%4];"
                 : "=r"(r[0]), "=r"(r[1]), "=r"(r[2]), "=r"(r[3]) : "r"(addr));
}
__device__ __forceinline__ void mma16816(float* c, const unsigned* a, unsigned b0, unsigned b1) {
    asm volatile(
        "mma.sync.aligned.m16n8k16.row.col.f32.bf16.bf16.f32 "
        "{%0,%1,%2,%3}, {%4,%5,%6,%7}, {%8,%9}, {%0,%1,%2,%3};"
        : "+f"(c[0]), "+f"(c[1]), "+f"(c[2]), "+f"(c[3])
        : "r"(a[0]), "r"(a[1]), "r"(a[2]), "r"(a[3]), "r"(b0), "r"(b1));
}

// ---------------------------------------------------------------------------
// Prologue: zero g_w, zero u, dtype probe
// ---------------------------------------------------------------------------
__global__ __launch_bounds__(256) void prologue(const unsigned int* __restrict__ s,
                                                float* __restrict__ u) {
    int blk = blockIdx.x;
    int tid = threadIdx.x;
    if (blk < 3125) {
        int i = blk * 256 + tid;
        float4 z = make_float4(0.f, 0.f, 0.f, 0.f);
        *(float4*)&g_w[(size_t)i * 4] = z;
    } else if (blk == 3125) {
        for (int i = tid; i < BB * DD; i += 256) u[i] = 0.f;
    } else if (tid < 32) {
        unsigned int acc = 0;
        #pragma unroll
        for (int i = tid; i < 256; i += 32) acc |= s[2 * i + 1];
        #pragma unroll
        for (int o = 16; o; o >>= 1) acc |= __shfl_xor_sync(0xffffffffu, acc, o);
        if (tid == 0) g_is64 = (acc == 0) ? 1 : 0;
    }
}

// ---------------------------------------------------------------------------
// Load 4 tokens of (m, b) from story (int64 or int32)
// ---------------------------------------------------------------------------
__device__ __forceinline__ void load_toks(const void* story, int is64, int m, int b,
                                          int* toks) {
    if (is64) {
        const long long* sp = (const long long*)story + (size_t)m * (BB * TT) + b * TT;
        longlong2 t0 = ((const longlong2*)sp)[0];
        longlong2 t1 = ((const longlong2*)sp)[1];
        toks[0] = (int)t0.x; toks[1] = (int)t0.y;
        toks[2] = (int)t1.x; toks[3] = (int)t1.y;
    } else {
        int4 tt = *((const int4*)((const int*)story + (size_t)m * (BB * TT) + b * TT));
        toks[0] = tt.x; toks[1] = tt.y; toks[2] = tt.z; toks[3] = tt.w;
    }
}

// ---------------------------------------------------------------------------
// attn_score: 256 blocks = (b, quarter). Each thread one m. Computes score
// via p-gather, local softmax numerator exp(s - Lmax), per-quarter (max, sum).
// ---------------------------------------------------------------------------
__global__ __launch_bounds__(512) void attn_score(const void* __restrict__ story) {
    int b = blockIdx.x >> 2;
    int q = blockIdx.x & 3;
    int tid = threadIdx.x;
    int m = q * 512 + tid;
    __shared__ float red[16];

    int is64 = g_is64;
    int toks[4];
    load_toks(story, is64, m, b, toks);

    float s = 0.f;
    #pragma unroll
    for (int t = 0; t < 4; t++)
        if (toks[t]) s += __ldg(&g_p[(size_t)toks[t] * BB + b]);

    float mx = s;
    #pragma unroll
    for (int o = 16; o; o >>= 1) mx = fmaxf(mx, __shfl_xor_sync(0xffffffffu, mx, o));
    if ((tid & 31) == 0) red[tid >> 5] = mx;
    __syncthreads();
    float bm = red[0];
    #pragma unroll
    for (int i = 1; i < 16; i++) bm = fmaxf(bm, red[i]);

    float e = __expf(s - bm);
    g_s[(size_t)b * MM + m] = e;

    float sum = e;
    #pragma unroll
    for (int o = 16; o; o >>= 1) sum += __shfl_xor_sync(0xffffffffu, sum, o);
    __syncthreads();
    if ((tid & 31) == 0) red[tid >> 5] = sum;
    __syncthreads();
    if (tid == 0) {
        float tot = 0.f;
        #pragma unroll
        for (int i = 0; i < 16; i++) tot += red[i];
        g_red[b * 4 + q] = make_float2(bm, tot);
    }
}

// ---------------------------------------------------------------------------
// attn_scatter: combines per-quarter (max,sum) into exact softmax scale,
// scatters prob into g_w. Hop 0: uniform prob.
// ---------------------------------------------------------------------------
__global__ __launch_bounds__(512) void attn_scatter(const void* __restrict__ story,
                                                    int use_p) {
    int b = blockIdx.x >> 2;
    int q = blockIdx.x & 3;
    int tid = threadIdx.x;
    int m = q * 512 + tid;

    int is64 = g_is64;
    int toks[4];
    load_toks(story, is64, m, b, toks);

    float prob;
    if (use_p) {
        float2 r0 = g_red[b * 4 + 0];
        float2 r1 = g_red[b * 4 + 1];
        float2 r2 = g_red[b * 4 + 2];
        float2 r3 = g_red[b * 4 + 3];
        float M = fmaxf(fmaxf(r0.x, r1.x), fmaxf(r2.x, r3.x));
        float total = r0.y * __expf(r0.x - M) + r1.y * __expf(r1.x - M)
                    + r2.y * __expf(r2.x - M) + r3.y * __expf(r3.x - M);
        float myb = (q == 0) ? r0.x : (q == 1) ? r1.x : (q == 2) ? r2.x : r3.x;
        float scale = __expf(myb - M) / total;
        prob = g_s[(size_t)b * MM + m] * scale;
    } else {
        prob = 1.0f / (float)MM;
    }

    float* wb = g_w + (size_t)b * VV;
    #pragma unroll
    for (int t = 0; t < 4; t++)
        if (toks[t]) atomicAdd(&wb[toks[t]], prob);
}

// ---------------------------------------------------------------------------
// p_gemm_mma: p[v][b] = sum_k Ct[v][k] * u[b][k], 512 threads / 16 warps.
// ---------------------------------------------------------------------------
__global__ __launch_bounds__(512, 2) void p_gemm_mma(const float* __restrict__ Ct,
                                                     const float* __restrict__ u) {
    extern __shared__ char dsm[];
    unsigned sbase = smem_u32(dsm);
    const unsigned A_HI = 0, A_LO = 32768, B_HI = 65536, B_LO = 81920;

    int tid = threadIdx.x;
    int wid = tid >> 5;
    int lane = tid & 31;
    int mw = wid & 7;
    int nh = wid >> 3;
    int vbase = blockIdx.x * 128;

    #pragma unroll
    for (int q = 0; q < 4; q++) {
        int fi = tid + q * 512;
        int row = fi >> 4;
        int c16 = fi & 15;
        int v = vbase + row;
        float4 f0 = make_float4(0.f, 0.f, 0.f, 0.f), f1 = f0;
        if (v < VV) {
            const float* src = Ct + (size_t)v * DD + c16 * 8;
            f0 = *(const float4*)src;
            f1 = *(const float4*)(src + 4);
        }
        uint4 hi, lo;
        split2(f0.x, f0.y, hi.x, lo.x);
        split2(f0.z, f0.w, hi.y, lo.y);
        split2(f1.x, f1.y, hi.z, lo.z);
        split2(f1.z, f1.w, hi.w, lo.w);
        unsigned off = (unsigned)(row * 256 + ((c16 ^ (row & 7)) << 4));
        *(uint4*)(dsm + A_HI + off) = hi;
        *(uint4*)(dsm + A_LO + off) = lo;
    }
    #pragma unroll
    for (int q = 0; q < 2; q++) {
        int fi = tid + q * 512;
        int row = fi >> 4;
        int c16 = fi & 15;
        const float* src = u + row * DD + c16 * 8;
        float4 f0 = *(const float4*)src;
        float4 f1 = *(const float4*)(src + 4);
        uint4 hi, lo;
        split2(f0.x, f0.y, hi.x, lo.x);
        split2(f0.z, f0.w, hi.y, lo.y);
        split2(f1.x, f1.y, hi.z, lo.z);
        split2(f1.z, f1.w, hi.w, lo.w);
        unsigned off = (unsigned)(row * 256 + ((c16 ^ (row & 7)) << 4));
        *(uint4*)(dsm + B_HI + off) = hi;
        *(uint4*)(dsm + B_LO + off) = lo;
    }
    __syncthreads();

    int mi = lane >> 3, r8 = lane & 7;
    int rowA = mw * 16 + (mi & 1) * 8 + r8;
    int kselA = mi >> 1;
    unsigned baseA = sbase + (unsigned)rowA * 256;
    int sA = rowA & 7;
    int rowB_off = ((lane >> 4) & 1) * 8 + r8;
    int kselB = (lane >> 3) & 1;

    float acc[4][4];
    #pragma unroll
    for (int na = 0; na < 4; na++)
        #pragma unroll
        for (int j = 0; j < 4; j++) acc[na][j] = 0.f;

    #pragma unroll
    for (int ks = 0; ks < 8; ks++) {
        unsigned a_hi[4], a_lo[4];
        unsigned cA = (unsigned)(((2 * ks + kselA) ^ sA) << 4);
        ldsm_x4(a_hi, baseA + A_HI + cA);
        ldsm_x4(a_lo, baseA + A_LO + cA);
        #pragma unroll
        for (int pa = 0; pa < 2; pa++) {
            int rowB = (nh * 2 + pa) * 16 + rowB_off;
            unsigned baseB = sbase + (unsigned)rowB * 256;
            unsigned cB = (unsigned)(((2 * ks + kselB) ^ (rowB & 7)) << 4);
            unsigned bh[4], bl[4];
            ldsm_x4(bh, baseB + B_HI + cB);
            ldsm_x4(bl, baseB + B_LO + cB);
            mma16816(acc[2 * pa],     a_hi, bh[0], bh[1]);
            mma16816(acc[2 * pa],     a_hi, bl[0], bl[1]);
            mma16816(acc[2 * pa],     a_lo, bh[0], bh[1]);
            mma16816(acc[2 * pa + 1], a_hi, bh[2], bh[3]);
            mma16816(acc[2 * pa + 1], a_hi, bl[2], bl[3]);
            mma16816(acc[2 * pa + 1], a_lo, bh[2], bh[3]);
        }
    }

    int v0 = vbase + mw * 16 + (lane >> 2);
    int bq = (lane & 3) * 2;
    #pragma unroll
    for (int na = 0; na < 4; na++) {
        int b0 = nh * 32 + na * 8 + bq;
        if (v0 < VV)
            *(float2*)&g_p[(size_t)v0 * BB + b0] = make_float2(acc[na][0], acc[na][1]);
        if (v0 + 8 < VV)
            *(float2*)&g_p[(size_t)(v0 + 8) * BB + b0] = make_float2(acc[na][2], acc[na][3]);
    }
}

// ---------------------------------------------------------------------------
// o_gemm_mma: partial[b][d] = sum_v w[b][v] * Ct[v][d] over this block's
// v-chunk. Epilogue: smem-stage acc -> COALESCED store to g_part[blk]
// (replaces 2.1M contended atomics). Reduce kernel folds into u.
// ---------------------------------------------------------------------------
__global__ __launch_bounds__(256) void o_gemm_mma(const float* __restrict__ Ct,
                                                  int do_zero) {
    __shared__ __align__(16) char osm[24576];
    __shared__ __align__(16) float obuf[64 * 132];
    const unsigned C_HI = 0, C_LO = 8192, W_HI = 16384, W_LO = 20480;
    unsigned sbase = smem_u32(osm);

    int tid = threadIdx.x;
    int wid = tid >> 5;
    int lane = tid & 31;
    int mw = wid & 3;
    int nw = wid >> 2;
    int vstart = blockIdx.x * (OG_TILES * 32);

    int sc_row = tid >> 5, sc4 = tid & 31;

    float4 rc[4], rw[2];
    {
        int vb = vstart;
        #pragma unroll
        for (int q = 0; q < 4; q++) {
            int v = vb + sc_row + q * 8;
            rc[q] = make_float4(0.f, 0.f, 0.f, 0.f);
            if (v < VV) rc[q] = *(const float4*)(Ct + (size_t)v * DD + sc4 * 4);
        }
        #pragma unroll
        for (int q = 0; q < 2; q++) {
            int fi = tid + q * 256;
            int b_ = fi >> 3, v4 = fi & 7;
            int v = vb + v4 * 4;
            rw[q] = make_float4(0.f, 0.f, 0.f, 0.f);
            if (v < VV) rw[q] = *(const float4*)(g_w + (size_t)b_ * VV + v);
        }
    }

    float acc[8][4];
    #pragma unroll
    for (int na = 0; na < 8; na++)
        #pragma unroll
        for (int j = 0; j < 4; j++) acc[na][j] = 0.f;

    int g = lane >> 3, r8 = lane & 7;
    unsigned a_roff = (unsigned)(((g >> 1) * 8 + r8) * 128
                                 + (((mw * 2 + (g & 1)) ^ r8) << 4));
    unsigned b_rbase = (unsigned)(((g & 1) * 8 + r8) * 256);
    int b_cxor = (nw * 8 + (g >> 1));

    #pragma unroll 1
    for (int t = 0; t < OG_TILES; t++) {
        __syncthreads();
        #pragma unroll
        for (int q = 0; q < 4; q++) {
            int row = sc_row + q * 8;
            float4 f = rc[q];
            uint2 hi, lo;
            split2(f.x, f.y, hi.x, lo.x);
            split2(f.z, f.w, hi.y, lo.y);
            unsigned off = (unsigned)(row * 256 + (((sc4 >> 1) ^ (row & 7)) << 4)
                                      + (sc4 & 1) * 8);
            *(uint2*)(osm + C_HI + off) = hi;
            *(uint2*)(osm + C_LO + off) = lo;
        }
        #pragma unroll
        for (int q = 0; q < 2; q++) {
            int fi = tid + q * 256;
            int b_ = fi >> 3, v4 = fi & 7;
            float fv[4] = {rw[q].x, rw[q].y, rw[q].z, rw[q].w};
            #pragma unroll
            for (int j = 0; j < 4; j++) {
                int vr = v4 * 4 + j;
                unsigned bx = __float_as_uint(fv[j]);
                float l = fv[j] - __uint_as_float(bx & 0xFFFF0000u);
                unsigned off = (unsigned)(vr * 128 + (((b_ >> 3) ^ (vr & 7)) << 4)
                                          + (b_ & 7) * 2);
                *(unsigned short*)(osm + W_HI + off) = (unsigned short)(bx >> 16);
                *(__nv_bfloat16*)(osm + W_LO + off) = __float2bfloat16(l);
            }
        }
        __syncthreads();

        if (t + 1 < OG_TILES) {
            int vb = vstart + (t + 1) * 32;
            #pragma unroll
            for (int q = 0; q < 4; q++) {
                int v = vb + sc_row + q * 8;
                rc[q] = make_float4(0.f, 0.f, 0.f, 0.f);
                if (v < VV) rc[q] = *(const float4*)(Ct + (size_t)v * DD + sc4 * 4);
            }
            #pragma unroll
            for (int q = 0; q < 2; q++) {
                int fi = tid + q * 256;
                int b_ = fi >> 3, v4 = fi & 7;
                int v = vb + v4 * 4;
                rw[q] = make_float4(0.f, 0.f, 0.f, 0.f);
                if (v < VV) rw[q] = *(const float4*)(g_w + (size_t)b_ * VV + v);
            }
        }

        #pragma unroll
        for (int ks = 0; ks < 2; ks++) {
            unsigned a_hi[4], a_lo[4];
            unsigned aoff = (unsigned)(ks * 16 * 128) + a_roff;
            ldsm_x4_t(a_hi, sbase + W_HI + aoff);
            ldsm_x4_t(a_lo, sbase + W_LO + aoff);
            #pragma unroll
            for (int pn = 0; pn < 4; pn++) {
                unsigned boff = (unsigned)(ks * 16 * 256) + b_rbase
                              + (unsigned)(((b_cxor + pn * 2) ^ r8) << 4);
                unsigned bh[4], bl[4];
                ldsm_x4_t(bh, sbase + C_HI + boff);
                ldsm_x4_t(bl, sbase + C_LO + boff);
                mma16816(acc[2 * pn],     a_hi, bh[0], bh[1]);
                mma16816(acc[2 * pn],     a_hi, bl[0], bl[1]);
                mma16816(acc[2 * pn],     a_lo, bh[0], bh[1]);
                mma16816(acc[2 * pn + 1], a_hi, bh[2], bh[3]);
                mma16816(acc[2 * pn + 1], a_hi, bl[2], bl[3]);
                mma16816(acc[2 * pn + 1], a_lo, bh[2], bh[3]);
            }
        }
    }

    // epilogue: acc -> smem (padded rows) -> coalesced partial store
    int br0 = mw * 16 + (lane >> 2);
    int nq = (lane & 3) * 2;
    #pragma unroll
    for (int na = 0; na < 8; na++) {
        int d = nw * 64 + na * 8 + nq;
        obuf[br0 * 132 + d]           = acc[na][0];
        obuf[br0 * 132 + d + 1]       = acc[na][1];
        obuf[(br0 + 8) * 132 + d]     = acc[na][2];
        obuf[(br0 + 8) * 132 + d + 1] = acc[na][3];
    }
    __syncthreads();
    {
        float* dst = g_part + (size_t)blockIdx.x * (BB * DD);
        #pragma unroll
        for (int q = 0; q < 8; q++) {
            int i4 = tid + q * 256;        // float4 index, 0..2047
            int b_ = i4 >> 5, d4 = i4 & 31;
            float4 val = *(float4*)&obuf[b_ * 132 + d4 * 4];
            *(float4*)&dst[b_ * DD + d4 * 4] = val;
        }
    }

    if (do_zero) {
        float4 z = make_float4(0.f, 0.f, 0.f, 0.f);
        for (int idx = tid; idx < 64 * 48; idx += 256) {
            int b_ = idx / 48;
            int v = vstart + (idx % 48) * 4;
            if (v < VV)
                *(float4*)&g_w[(size_t)b_ * VV + v] = z;
        }
    }
}

// ---------------------------------------------------------------------------
// reduce_part: u[i] += sum over 261 blocks of g_part[blk][i].
// 65536 threads (8 groups x 8192 i) -> ~33 loads/thread, coalesced, MLP-rich;
// 8-way atomics per address (cheap).
// ---------------------------------------------------------------------------
__global__ __launch_bounds__(256) void reduce_part(float* __restrict__ u) {
    int t = blockIdx.x * 256 + threadIdx.x;   // 0..65535
    int i = t & (BB * DD - 1);
    int g = t >> 13;                           // 0..7
    float s = 0.f;
    for (int k = g; k < OG_GRID; k += 8)
        s += g_part[(size_t)k * (BB * DD) + i];
    atomicAdd(&u[i], s);
}

// ---------------------------------------------------------------------------
extern "C" void kernel_launch(void* const* d_in, const int* in_sizes, int n_in,
                              void* d_out, int out_size) {
    int si = 0, ci = 1;
    if (n_in >= 2 && in_sizes[0] > in_sizes[1]) { si = 1; ci = 0; }
    const void* story = d_in[si];
    const float* C = (const float*)d_in[ci];
    float* u = (float*)d_out;

    const int PG_SMEM = 98304;   // A hi/lo 32K*2 + B hi/lo 16K*2
    static int smem_set = 0;
    if (!smem_set) {
        cudaFuncSetAttribute(p_gemm_mma, cudaFuncAttributeMaxDynamicSharedMemorySize, PG_SMEM);
        smem_set = 1;
    }

    prologue<<<3127, 256>>>((const unsigned int*)story, u);

    for (int h = 0; h < 3; h++) {
        if (h) {
            p_gemm_mma<<<PG_GRID, 512, PG_SMEM>>>(C + (size_t)h * VV * DD, u);
            attn_score<<<BB * 4, 512>>>(story);
        }
        attn_scatter<<<BB * 4, 512>>>(story, h > 0 ? 1 : 0);
        o_gemm_mma<<<OG_GRID, 256>>>(C + (size_t)(h + 1) * VV * DD, h < 2 ? 1 : 0);
        reduce_part<<<256, 256>>>(u);
    }
}